// round 2
// baseline (speedup 1.0000x reference)
#include <cuda_runtime.h>
#include <math.h>

#define T_STEPS 500
#define BATCH   128
#define FDIM    128
#define HDIM    512
#define ODIM    32

// Scratch (device globals — the sanctioned allocation-free path)
__device__ float g_iin[T_STEPS * BATCH * HDIM];   // 131 MB: precomputed x @ W_in^T
__device__ float g_wrecT[HDIM * HDIM];            // W_rec transposed: [src][dst]
__device__ float g_woutT[HDIM * ODIM];            // W_out transposed: [h][o]

// ---------------------------------------------------------------------------
// Transpose W_rec and W_out for coalesced gather access
// ---------------------------------------------------------------------------
__global__ void transpose_kernel(const float* __restrict__ W_rec,
                                 const float* __restrict__ W_out) {
    int idx = blockIdx.x * blockDim.x + threadIdx.x;
    if (idx < HDIM * HDIM) {
        int r = idx / HDIM, c = idx % HDIM;
        g_wrecT[c * HDIM + r] = W_rec[idx];
    }
    if (idx < ODIM * HDIM) {
        int o = idx / HDIM, h = idx % HDIM;
        g_woutT[h * ODIM + o] = W_out[idx];
    }
}

// ---------------------------------------------------------------------------
// GEMM: g_iin[m, n] = sum_k X[m, k] * W_in[n, k]
//   M = T*B = 64000, N = 512, K = 128.  Tiles 64x64x64, 256 thr, 4x4/thread.
// ---------------------------------------------------------------------------
#define BM 64
#define BN 64
#define BK 64

__global__ void __launch_bounds__(256) gemm_iin_kernel(
    const float* __restrict__ X, const float* __restrict__ Win) {
    __shared__ float As[BK][BM + 4];
    __shared__ float Bs[BK][BN + 4];

    int tid = threadIdx.x;
    int bm = blockIdx.y;           // 0..999
    int bn = blockIdx.x;           // 0..7
    const float* Xb = X   + (size_t)bm * BM * FDIM;
    const float* Wb = Win + (size_t)bn * BN * FDIM;

    int tx = tid & 15;             // n-group
    int ty = tid >> 4;             // m-group
    float acc[4][4] = {};

    for (int k0 = 0; k0 < FDIM; k0 += BK) {
        int kq = (tid & 15) * 4;
        int r0 = tid >> 4;
        #pragma unroll
        for (int rr = 0; rr < 4; rr++) {
            int r = r0 + rr * 16;
            float4 va = *(const float4*)(Xb + r * FDIM + k0 + kq);
            As[kq + 0][r] = va.x; As[kq + 1][r] = va.y;
            As[kq + 2][r] = va.z; As[kq + 3][r] = va.w;
            float4 vb = *(const float4*)(Wb + r * FDIM + k0 + kq);
            Bs[kq + 0][r] = vb.x; Bs[kq + 1][r] = vb.y;
            Bs[kq + 2][r] = vb.z; Bs[kq + 3][r] = vb.w;
        }
        __syncthreads();

        #pragma unroll
        for (int k = 0; k < BK; k++) {
            float4 a = *(const float4*)&As[k][ty * 4];
            float4 b = *(const float4*)&Bs[k][tx * 4];
            acc[0][0] += a.x * b.x; acc[0][1] += a.x * b.y;
            acc[0][2] += a.x * b.z; acc[0][3] += a.x * b.w;
            acc[1][0] += a.y * b.x; acc[1][1] += a.y * b.y;
            acc[1][2] += a.y * b.z; acc[1][3] += a.y * b.w;
            acc[2][0] += a.z * b.x; acc[2][1] += a.z * b.y;
            acc[2][2] += a.z * b.z; acc[2][3] += a.z * b.w;
            acc[3][0] += a.w * b.x; acc[3][1] += a.w * b.y;
            acc[3][2] += a.w * b.z; acc[3][3] += a.w * b.w;
        }
        __syncthreads();
    }

    float* C = g_iin + (size_t)(bm * BM) * HDIM + bn * BN;
    #pragma unroll
    for (int i = 0; i < 4; i++) {
        float4 v;
        v.x = acc[i][0]; v.y = acc[i][1]; v.z = acc[i][2]; v.w = acc[i][3];
        *(float4*)(C + (size_t)(ty * 4 + i) * HDIM + tx * 4) = v;
    }
}

// ---------------------------------------------------------------------------
// Persistent SNN kernel: one CTA per batch element, 512 threads = 512 neurons.
// All 500 timesteps run inside the kernel (no cross-CTA dependency).
// Spike-list (sparse) recurrent gather + in-kernel readout & IIR filter.
// ---------------------------------------------------------------------------
__global__ void __launch_bounds__(512) snn_kernel(
    const float* __restrict__ b_out, float* __restrict__ out) {
    const int b    = blockIdx.x;
    const int tid  = threadIdx.x;
    const int lane = tid & 31;
    const int warp = tid >> 5;

    __shared__ int s_list[HDIM];
    __shared__ int s_wcnt[16];

    float v = 0.f, icur = 0.f, a = 0.f;
    float o_state = 0.f;
    float bo = 0.f;
    if (warp == 0) bo = b_out[lane];
    if (tid < 16) s_wcnt[tid] = 0;
    __syncthreads();

    const float* iin_b = g_iin + (size_t)b * HDIM;
    float*       out_b = out   + (size_t)b * ODIM;

    int n = 0;  // active spike count of previous step (z0 = 0)

    for (int t = 0; t < T_STEPS; t++) {
        // feed-forward current for this step (streamed from HBM; hidden by gather)
        float ic = iin_b[(size_t)t * BATCH * HDIM + tid];

        // sparse recurrent current: sum of W_rec columns at active indices
        float rec = 0.f;
        int j = 0;
        for (; j + 4 <= n; j += 4) {
            int i0 = s_list[j + 0];
            int i1 = s_list[j + 1];
            int i2 = s_list[j + 2];
            int i3 = s_list[j + 3];
            float w0 = g_wrecT[i0 * HDIM + tid];
            float w1 = g_wrecT[i1 * HDIM + tid];
            float w2 = g_wrecT[i2 * HDIM + tid];
            float w3 = g_wrecT[i3 * HDIM + tid];
            rec += ((w0 + w1) + (w2 + w3));
        }
        for (; j < n; j++) rec += g_wrecT[s_list[j] * HDIM + tid];

        // LIF-AdEx state update (grouping mirrors the JAX reference)
        float dv    = 0.1f * ((((0.0f - v) + 0.5f * expf((v - 1.0f) * 2.0f)) + icur) - a);
        float v_dec = v + dv;
        float i_dec = icur - 0.2f * icur;
        float a_dec = a + 0.002f * (4.0f * v - a);
        int   z_new = (v_dec - 1.0f) > 0.0f;
        float v_new = z_new ? 0.0f : v_dec;
        icur = (i_dec + ic) + rec;
        a    = a_dec + (z_new ? 0.02f : 0.0f);
        v    = v_new;

        // ---- build new spike list (deterministic ballot-scan compaction) ----
        __syncthreads();                       // everyone done reading s_list
        unsigned ballot = __ballot_sync(0xffffffffu, z_new);
        if (lane == 0) s_wcnt[warp] = __popc(ballot);
        __syncthreads();                       // counts visible

        int base = 0, ntot = 0;
        #pragma unroll
        for (int w = 0; w < 16; w++) {
            int c = s_wcnt[w];
            if (w < warp) base += c;
            ntot += c;
        }
        int pos = base + __popc(ballot & ((1u << lane) - 1u));
        if (z_new) s_list[pos] = tid;
        n = ntot;
        __syncthreads();                       // list complete

        // ---- readout + exp filter (warp 0; others run ahead to next gather) ----
        if (warp == 0) {
            float accy = 0.f;
            for (int jj = 0; jj < n; jj++)
                accy += g_woutT[s_list[jj] * ODIM + lane];
            float y = accy + bo;
            o_state = (t == 0) ? y : o_state + 0.2231435511314f * (y - o_state);
            out_b[(size_t)t * BATCH * ODIM + lane] = o_state;
        }
    }
}

// ---------------------------------------------------------------------------
extern "C" void kernel_launch(void* const* d_in, const int* in_sizes, int n_in,
                              void* d_out, int out_size) {
    const float* x     = (const float*)d_in[0];  // (T,B,F)
    const float* W_in  = (const float*)d_in[1];  // (H,F)
    const float* W_rec = (const float*)d_in[2];  // (H,H)
    const float* W_out = (const float*)d_in[3];  // (O,H)
    const float* b_out = (const float*)d_in[4];  // (O,)
    float* out = (float*)d_out;                  // (T,B,O)

    transpose_kernel<<<(HDIM * HDIM + 255) / 256, 256>>>(W_rec, W_out);

    dim3 ggrid(HDIM / BN, (T_STEPS * BATCH) / BM);  // (8, 1000)
    gemm_iin_kernel<<<ggrid, 256>>>(x, W_in);

    snn_kernel<<<BATCH, 512>>>(b_out, out);
}

// round 3
// speedup vs baseline: 1.0036x; 1.0036x over previous
#include <cuda_runtime.h>
#include <math.h>

#define T_STEPS 500
#define BATCH   128
#define FDIM    128
#define HDIM    512
#define ODIM    32

// Scratch (device globals — the sanctioned allocation-free path)
__device__ float g_iin[T_STEPS * BATCH * HDIM];   // 131 MB: precomputed x @ W_in^T
__device__ float g_wrecT[HDIM * HDIM];            // W_rec transposed: [src][dst]
__device__ float g_woutT[HDIM * ODIM];            // W_out transposed: [h][o]

// ---------------------------------------------------------------------------
// Transpose W_rec and W_out for coalesced gather access
// ---------------------------------------------------------------------------
__global__ void transpose_kernel(const float* __restrict__ W_rec,
                                 const float* __restrict__ W_out) {
    int idx = blockIdx.x * blockDim.x + threadIdx.x;
    if (idx < HDIM * HDIM) {
        int r = idx / HDIM, c = idx % HDIM;
        g_wrecT[c * HDIM + r] = W_rec[idx];
    }
    if (idx < ODIM * HDIM) {
        int o = idx / HDIM, h = idx % HDIM;
        g_woutT[h * ODIM + o] = W_out[idx];
    }
}

// ---------------------------------------------------------------------------
// GEMM: g_iin[m, n] = sum_k X[m, k] * W_in[n, k]
//   M = 64000, N = 512, K = 128.  BM=BN=128, BK=32, 256 thr, 8x8 per thread.
//   FFMA-bound: per k-step 256 cyc FFMA vs 128 cyc LDS per block.
// ---------------------------------------------------------------------------
#define GBM 128
#define GBN 128
#define GBK 32

__global__ void __launch_bounds__(256) gemm_iin_kernel(
    const float* __restrict__ X, const float* __restrict__ Win) {
    __shared__ float As[GBK][GBM + 4];
    __shared__ float Bs[GBK][GBN + 4];

    const int tid = threadIdx.x;
    const int bm = blockIdx.y;          // 0..499
    const int bn = blockIdx.x;          // 0..3
    const float* Xb = X   + (size_t)bm * GBM * FDIM;
    const float* Wb = Win + (size_t)bn * GBN * FDIM;

    const int ty = tid >> 4;            // 0..15 (m-group)
    const int tx = tid & 15;            // 0..15 (n-group)
    const int lrow = tid >> 3;          // 0..31
    const int lcol = (tid & 7) * 4;     // 0,4,...,28

    float acc[8][8] = {};

    for (int k0 = 0; k0 < FDIM; k0 += GBK) {
        #pragma unroll
        for (int p = 0; p < 4; p++) {
            int r = lrow + p * 32;
            float4 va = *(const float4*)(Xb + (size_t)r * FDIM + k0 + lcol);
            As[lcol + 0][r] = va.x; As[lcol + 1][r] = va.y;
            As[lcol + 2][r] = va.z; As[lcol + 3][r] = va.w;
            float4 vb = *(const float4*)(Wb + (size_t)r * FDIM + k0 + lcol);
            Bs[lcol + 0][r] = vb.x; Bs[lcol + 1][r] = vb.y;
            Bs[lcol + 2][r] = vb.z; Bs[lcol + 3][r] = vb.w;
        }
        __syncthreads();

        #pragma unroll
        for (int k = 0; k < GBK; k++) {
            float af[8], bf[8];
            *(float4*)(af)     = *(const float4*)&As[k][ty * 8];
            *(float4*)(af + 4) = *(const float4*)&As[k][ty * 8 + 4];
            *(float4*)(bf)     = *(const float4*)&Bs[k][tx * 8];
            *(float4*)(bf + 4) = *(const float4*)&Bs[k][tx * 8 + 4];
            #pragma unroll
            for (int i = 0; i < 8; i++)
                #pragma unroll
                for (int j = 0; j < 8; j++)
                    acc[i][j] += af[i] * bf[j];
        }
        __syncthreads();
    }

    float* C = g_iin + (size_t)(bm * GBM) * HDIM + bn * GBN;
    #pragma unroll
    for (int i = 0; i < 8; i++) {
        float4 v0, v1;
        v0.x = acc[i][0]; v0.y = acc[i][1]; v0.z = acc[i][2]; v0.w = acc[i][3];
        v1.x = acc[i][4]; v1.y = acc[i][5]; v1.z = acc[i][6]; v1.w = acc[i][7];
        float* Crow = C + (size_t)(ty * 8 + i) * HDIM + tx * 8;
        *(float4*)(Crow)     = v0;
        *(float4*)(Crow + 4) = v1;
    }
}

// ---------------------------------------------------------------------------
// Persistent SNN kernel: one CTA per batch element, 512 threads.
// Gather restructured for MLP: 4 j-slices x 128 threads, float4 row chunks,
// 4 independent accumulators (chain length n/16 instead of n/4).
// ---------------------------------------------------------------------------
__global__ void __launch_bounds__(512) snn_kernel(
    const float* __restrict__ b_out, float* __restrict__ out) {
    const int b     = blockIdx.x;
    const int tid   = threadIdx.x;
    const int lane  = tid & 31;
    const int warp  = tid >> 5;
    const int slice = tid >> 7;        // 0..3
    const int h4    = tid & 127;       // float4 chunk within a row

    __shared__ int   s_list[HDIM];
    __shared__ int   s_wcnt[16];
    __shared__ float s_red[4][HDIM];   // per-slice partial rec

    float v = 0.f, icur = 0.f, a = 0.f;
    float o_state = 0.f;
    float bo = 0.f;
    if (warp == 0) bo = b_out[lane];
    if (tid < 16) s_wcnt[tid] = 0;
    __syncthreads();

    const float* iin_b = g_iin + (size_t)b * HDIM + tid;
    float*       out_b = out   + (size_t)b * ODIM;
    const float* wbase = g_wrecT + (h4 << 2);

    int n = 0;                         // active spikes of previous step
    float ic = iin_b[0];               // prefetched feed-forward current (t=0)

    for (int t = 0; t < T_STEPS; t++) {
        // prefetch next step's feed-forward current (hides DRAM latency)
        float ic_next = 0.f;
        if (t + 1 < T_STEPS)
            ic_next = __ldg(iin_b + (size_t)(t + 1) * BATCH * HDIM);

        // ---- sparse recurrent gather: slice handles j = slice, slice+4, ... ----
        float4 a0 = {0,0,0,0}, a1 = {0,0,0,0}, a2 = {0,0,0,0}, a3 = {0,0,0,0};
        int j = slice;
        for (; j + 12 < n; j += 16) {
            float4 w0 = *(const float4*)(wbase + (size_t)s_list[j]      * HDIM);
            float4 w1 = *(const float4*)(wbase + (size_t)s_list[j + 4]  * HDIM);
            float4 w2 = *(const float4*)(wbase + (size_t)s_list[j + 8]  * HDIM);
            float4 w3 = *(const float4*)(wbase + (size_t)s_list[j + 12] * HDIM);
            a0.x += w0.x; a0.y += w0.y; a0.z += w0.z; a0.w += w0.w;
            a1.x += w1.x; a1.y += w1.y; a1.z += w1.z; a1.w += w1.w;
            a2.x += w2.x; a2.y += w2.y; a2.z += w2.z; a2.w += w2.w;
            a3.x += w3.x; a3.y += w3.y; a3.z += w3.z; a3.w += w3.w;
        }
        for (; j < n; j += 4) {
            float4 w = *(const float4*)(wbase + (size_t)s_list[j] * HDIM);
            a0.x += w.x; a0.y += w.y; a0.z += w.z; a0.w += w.w;
        }
        a0.x += a1.x + a2.x + a3.x;
        a0.y += a1.y + a2.y + a3.y;
        a0.z += a1.z + a2.z + a3.z;
        a0.w += a1.w + a2.w + a3.w;
        *(float4*)&s_red[slice][h4 << 2] = a0;
        __syncthreads();

        float rec = (s_red[0][tid] + s_red[1][tid]) + (s_red[2][tid] + s_red[3][tid]);

        // ---- LIF-AdEx state update (grouping mirrors the JAX reference) ----
        float dv    = 0.1f * ((((0.0f - v) + 0.5f * expf((v - 1.0f) * 2.0f)) + icur) - a);
        float v_dec = v + dv;
        float i_dec = icur - 0.2f * icur;
        float a_dec = a + 0.002f * (4.0f * v - a);
        int   z_new = (v_dec - 1.0f) > 0.0f;
        v    = z_new ? 0.0f : v_dec;
        icur = (i_dec + ic) + rec;
        a    = a_dec + (z_new ? 0.02f : 0.0f);

        // ---- build new spike list (deterministic ballot-scan compaction) ----
        unsigned ballot = __ballot_sync(0xffffffffu, z_new);
        if (lane == 0) s_wcnt[warp] = __popc(ballot);
        __syncthreads();

        int base = 0, ntot = 0;
        #pragma unroll
        for (int w = 0; w < 16; w++) {
            int c = s_wcnt[w];
            if (w < warp) base += c;
            ntot += c;
        }
        int pos = base + __popc(ballot & ((1u << lane) - 1u));
        if (z_new) s_list[pos] = tid;
        n = ntot;
        __syncthreads();

        // ---- readout + exp filter (warp 0; other warps race ahead to gather) ----
        if (warp == 0) {
            float y0 = 0.f, y1 = 0.f, y2 = 0.f, y3 = 0.f;
            int jj = 0;
            for (; jj + 3 < n; jj += 4) {
                y0 += g_woutT[s_list[jj]     * ODIM + lane];
                y1 += g_woutT[s_list[jj + 1] * ODIM + lane];
                y2 += g_woutT[s_list[jj + 2] * ODIM + lane];
                y3 += g_woutT[s_list[jj + 3] * ODIM + lane];
            }
            for (; jj < n; jj++)
                y0 += g_woutT[s_list[jj] * ODIM + lane];
            float y = ((y0 + y1) + (y2 + y3)) + bo;
            o_state = (t == 0) ? y : o_state + 0.2231435511314f * (y - o_state);
            out_b[(size_t)t * BATCH * ODIM + lane] = o_state;
        }

        ic = ic_next;
    }
}

// ---------------------------------------------------------------------------
extern "C" void kernel_launch(void* const* d_in, const int* in_sizes, int n_in,
                              void* d_out, int out_size) {
    const float* x     = (const float*)d_in[0];  // (T,B,F)
    const float* W_in  = (const float*)d_in[1];  // (H,F)
    const float* W_rec = (const float*)d_in[2];  // (H,H)
    const float* W_out = (const float*)d_in[3];  // (O,H)
    const float* b_out = (const float*)d_in[4];  // (O,)
    float* out = (float*)d_out;                  // (T,B,O)

    transpose_kernel<<<(HDIM * HDIM + 255) / 256, 256>>>(W_rec, W_out);

    dim3 ggrid(HDIM / GBN, (T_STEPS * BATCH) / GBM);  // (4, 500)
    gemm_iin_kernel<<<ggrid, 256>>>(x, W_in);

    snn_kernel<<<BATCH, 512>>>(b_out, out);
}